// round 7
// baseline (speedup 1.0000x reference)
#include <cuda_runtime.h>

// out[n,f] = kipf[n,f] - lbda[n] * input[n,f]
// N_NODES = 100000, N_FEATURES = 256 -> 25.6M floats = 6.4M float4, exact.
// Strictly HBM-bound: ~307.6 MB of traffic, target ~49 us at ~6.3 TB/s.

static constexpr int N_FEATURES = 256;
static constexpr int F4_PER_NODE = N_FEATURES / 4;       // 64 float4 per node

__global__ void __launch_bounds__(256) damping_kernel(
    const float4* __restrict__ input4,
    const float4* __restrict__ kipf4,
    const float*  __restrict__ lbda,
    float4*       __restrict__ out4)
{
    // Exact launch: grid * block == total float4 count (6.4M). No bounds check.
    const long long i = (long long)blockIdx.x * blockDim.x + threadIdx.x;

    // 64 consecutive threads share one node -> lbda load is a warp broadcast
    // and a guaranteed L1/L2 hit (400 KB total, fully cached).
    const int node = (int)(i >> 6);                       // i / F4_PER_NODE
    const float l = __ldg(&lbda[node]);

    // Two independent 128-bit loads issued back-to-back (MLP>=2 per thread,
    // thousands of warps in flight -> DRAM latency fully hidden).
    const float4 a = input4[i];
    const float4 b = kipf4[i];

    float4 r;
    r.x = fmaf(-l, a.x, b.x);
    r.y = fmaf(-l, a.y, b.y);
    r.z = fmaf(-l, a.z, b.z);
    r.w = fmaf(-l, a.w, b.w);

    out4[i] = r;
}

extern "C" void kernel_launch(void* const* d_in, const int* in_sizes, int n_in,
                              void* d_out, int out_size)
{
    // metadata order: input_term [100000*256 f32], kipf_term [100000*256 f32],
    //                 lbda [100000 f32], spar (int scalar, unused: always 1)
    const float4* input4 = (const float4*)d_in[0];
    const float4* kipf4  = (const float4*)d_in[1];
    const float*  lbda   = (const float*)d_in[2];
    float4*       out4   = (float4*)d_out;

    const long long total_f4 = (long long)in_sizes[0] / 4;   // 6,400,000
    const int threads = 256;
    const int blocks  = (int)((total_f4 + threads - 1) / threads);  // 25,000

    damping_kernel<<<blocks, threads>>>(input4, kipf4, lbda, out4);
}